// round 1
// baseline (speedup 1.0000x reference)
#include <cuda_runtime.h>
#include <math.h>

// Problem constants (fixed by reference)
#define VOCAB 100000
#define DIM   128
#define BATCH 16384
#define CTX   10
#define NEG   5

#define WARPS_PER_BLOCK 8
#define THREADS (WARPS_PER_BLOCK * 32)
#define NUM_BLOCKS (BATCH / WARPS_PER_BLOCK)   // 2048

// Scratch for per-block partial sums (no cudaMalloc allowed)
__device__ float g_partials[NUM_BLOCKS];

__device__ __forceinline__ float log_sigmoid(float x) {
    // stable: min(x,0) - log1p(exp(-|x|))
    return fminf(x, 0.0f) - log1pf(expf(-fabsf(x)));
}

__global__ __launch_bounds__(THREADS)
void cbow_loss_kernel(const int* __restrict__ pos_u,   // [B, CTX]
                      const int* __restrict__ pos_w,   // [B]
                      const int* __restrict__ neg_w,   // [B, NEG]
                      const float4* __restrict__ u_w,  // [VOCAB, 32] as float4
                      const float4* __restrict__ w_w)  // [VOCAB, 32] as float4
{
    const int warp = threadIdx.x >> 5;
    const int lane = threadIdx.x & 31;
    const int b = blockIdx.x * WARPS_PER_BLOCK + warp;

    // --- gather-sum context embeddings: u_sum[lane] = sum_c u_weight[pos_u[b,c]] ---
    float4 usum = make_float4(0.f, 0.f, 0.f, 0.f);
    const int* pu = pos_u + b * CTX;
    #pragma unroll
    for (int c = 0; c < CTX; ++c) {
        int idx = __ldg(pu + c);                 // uniform across warp
        float4 v = __ldg(u_w + idx * 32 + lane); // coalesced 512B row
        usum.x += v.x; usum.y += v.y; usum.z += v.z; usum.w += v.w;
    }

    // --- positive target row ---
    {
        int idx = __ldg(pos_w + b);
        float4 p = __ldg(w_w + idx * 32 + lane);
        float pd = usum.x * p.x + usum.y * p.y + usum.z * p.z + usum.w * p.w;

        // --- negative rows summed first (dot distributes) ---
        float4 nsum = make_float4(0.f, 0.f, 0.f, 0.f);
        const int* nw = neg_w + b * NEG;
        #pragma unroll
        for (int k = 0; k < NEG; ++k) {
            int idx2 = __ldg(nw + k);
            float4 v = __ldg(w_w + idx2 * 32 + lane);
            nsum.x += v.x; nsum.y += v.y; nsum.z += v.z; nsum.w += v.w;
        }
        float nd = usum.x * nsum.x + usum.y * nsum.y + usum.z * nsum.z + usum.w * nsum.w;

        // --- warp reduce both dots ---
        #pragma unroll
        for (int off = 16; off > 0; off >>= 1) {
            pd += __shfl_xor_sync(0xFFFFFFFFu, pd, off);
            nd += __shfl_xor_sync(0xFFFFFFFFu, nd, off);
        }

        __shared__ float s_part[WARPS_PER_BLOCK];
        if (lane == 0) {
            s_part[warp] = log_sigmoid(pd) + log_sigmoid(-nd);
        }
        __syncthreads();

        if (warp == 0 && lane == 0) {
            float acc = 0.f;
            #pragma unroll
            for (int i = 0; i < WARPS_PER_BLOCK; ++i) acc += s_part[i];
            g_partials[blockIdx.x] = acc;
        }
    }
}

__global__ __launch_bounds__(256)
void final_reduce_kernel(float* __restrict__ out)
{
    const int tid = threadIdx.x;
    double acc = 0.0;
    for (int i = tid; i < NUM_BLOCKS; i += 256)
        acc += (double)g_partials[i];

    // warp reduce (double via two shfls of the 64-bit value)
    #pragma unroll
    for (int off = 16; off > 0; off >>= 1)
        acc += __shfl_xor_sync(0xFFFFFFFFu, acc, off);

    __shared__ double s[8];
    if ((tid & 31) == 0) s[tid >> 5] = acc;
    __syncthreads();
    if (tid == 0) {
        double t = 0.0;
        #pragma unroll
        for (int i = 0; i < 8; ++i) t += s[i];
        out[0] = (float)(-t);   // loss = -(sum of logsigmoids)
    }
}

extern "C" void kernel_launch(void* const* d_in, const int* in_sizes, int n_in,
                              void* d_out, int out_size) {
    const int*   pos_u = (const int*)d_in[0];
    const int*   pos_w = (const int*)d_in[1];
    const int*   neg_w = (const int*)d_in[2];
    const float4* u_w  = (const float4*)d_in[3];
    const float4* w_w  = (const float4*)d_in[4];
    float* out = (float*)d_out;

    cbow_loss_kernel<<<NUM_BLOCKS, THREADS>>>(pos_u, pos_w, neg_w, u_w, w_w);
    final_reduce_kernel<<<1, 256>>>(out);
}